// round 4
// baseline (speedup 1.0000x reference)
#include <cuda_runtime.h>
#include <cuda_bf16.h>
#include <cstdint>

// Problem constants
#define TT 256
#define BB 64
#define EE 512
#define HH 1024
#define VV 10000
#define K1 1536      // E + H
#define G4 4096      // 4*H

// Scratch (no cudaMalloc allowed): device globals
__device__ float g_xemb[(size_t)TT * BB * EE];   // [T][B][E]  33.5 MB
__device__ float g_gbuf[(size_t)BB * G4];        // [B][4H] gate pre-activations, 1 MB

// ---------------------------------------------------------------------------
// Kernel 1: embedding gather  x_emb[t][b][:] = emb[x[t][b]][:]
// grid = T*B blocks, 128 threads; each thread copies one float4 (512 floats/row)
// ---------------------------------------------------------------------------
__global__ void embed_kernel(const int* __restrict__ x, const float* __restrict__ emb) {
    int row = blockIdx.x;                 // t*B + b
    int idx = x[row];
    const float4* src = (const float4*)(emb + (size_t)idx * EE);
    float4* dst = (float4*)(g_xemb + (size_t)row * EE);
    dst[threadIdx.x] = src[threadIdx.x];
}

// ---------------------------------------------------------------------------
// Kernel 2: per-step gate GEMM  g = [h_prev | x_t] @ W_gate   (bias added later)
// M=64, N=4096 (128 N-tiles of 32, one gate per block), K=1536
// BM=64, BN=32, BK=16, 128 threads, 4x4 microtile (thread grid 16x8)
// ---------------------------------------------------------------------------
__global__ void __launch_bounds__(128)
gate_gemm_kernel(const float* __restrict__ h_prev, int t,
                 const float* __restrict__ Wf, const float* __restrict__ Wi,
                 const float* __restrict__ Wc, const float* __restrict__ Wo) {
    __shared__ float As[16][64];   // [k][m]
    __shared__ float Bs[16][32];   // [k][n]

    const int nt   = blockIdx.x;          // 0..127
    const int gate = nt >> 5;             // 0..3
    const int col0 = (nt & 31) * 32;      // column within gate's H
    const float* W = (gate == 0) ? Wf : (gate == 1) ? Wi : (gate == 2) ? Wc : Wo;

    const int tid = threadIdx.x;
    const int tm = tid >> 3;              // 0..15
    const int tn = tid & 7;               // 0..7

    const float* xe = g_xemb + (size_t)t * BB * EE;

    float acc[4][4];
#pragma unroll
    for (int a = 0; a < 4; ++a)
#pragma unroll
        for (int b = 0; b < 4; ++b) acc[a][b] = 0.0f;

    for (int k0 = 0; k0 < K1; k0 += 16) {
        // ---- A tile: hx[m][k0..k0+15], transposed into As[k][m]
        const float* src;
        int stride, kb;
        if (k0 < HH) { src = h_prev; stride = HH; kb = k0; }
        else         { src = xe;     stride = EE; kb = k0 - HH; }
#pragma unroll
        for (int j = 0; j < 2; ++j) {
            int i = tid * 2 + j;              // 0..255
            int row = i >> 2;                 // 0..63
            int kq  = (i & 3) * 4;            // 0,4,8,12
            float4 v = *(const float4*)(src + (size_t)row * stride + kb + kq);
            As[kq + 0][row] = v.x;
            As[kq + 1][row] = v.y;
            As[kq + 2][row] = v.z;
            As[kq + 3][row] = v.w;
        }
        // ---- B tile: W[k0+kk][col0+nn], 16x32 = 128 float4 (one per thread)
        {
            int kk = tid >> 3;                // 0..15
            int nq = (tid & 7) * 4;           // 0..28
            float4 v = *(const float4*)(W + (size_t)(k0 + kk) * HH + col0 + nq);
            *(float4*)&Bs[kk][nq] = v;
        }
        __syncthreads();

#pragma unroll
        for (int kk = 0; kk < 16; ++kk) {
            float4 a = *(const float4*)&As[kk][tm * 4];
            float4 b = *(const float4*)&Bs[kk][tn * 4];
            float av[4] = {a.x, a.y, a.z, a.w};
            float bv[4] = {b.x, b.y, b.z, b.w};
#pragma unroll
            for (int mi = 0; mi < 4; ++mi)
#pragma unroll
                for (int ni = 0; ni < 4; ++ni)
                    acc[mi][ni] += av[mi] * bv[ni];
        }
        __syncthreads();
    }

#pragma unroll
    for (int mi = 0; mi < 4; ++mi) {
        int m = tm * 4 + mi;
        float* gp = g_gbuf + (size_t)m * G4 + gate * HH + col0 + tn * 4;
#pragma unroll
        for (int ni = 0; ni < 4; ++ni) gp[ni] = acc[mi][ni];
    }
}

// ---------------------------------------------------------------------------
// Kernel 3: LSTM cell pointwise: bias + activations + state update
// grid = B*H/256 blocks, 256 threads
// ---------------------------------------------------------------------------
__device__ __forceinline__ float sigmoidf_(float x) {
    return 1.0f / (1.0f + __expf(-x));
}

__global__ void __launch_bounds__(256)
cell_kernel(const float* __restrict__ c_prev,
            const float* __restrict__ bf, const float* __restrict__ bi,
            const float* __restrict__ bc, const float* __restrict__ bo,
            float* __restrict__ h_out, float* __restrict__ c_out) {
    int idx = blockIdx.x * blockDim.x + threadIdx.x;  // 0..B*H-1
    int b = idx >> 10;          // /H
    int j = idx & (HH - 1);     // %H
    const float* g = g_gbuf + (size_t)b * G4;
    float f  = sigmoidf_(g[j]           + bf[j]);
    float ii = sigmoidf_(g[HH + j]      + bi[j]);
    float cd = tanhf    (g[2 * HH + j]  + bc[j]);
    float o  = sigmoidf_(g[3 * HH + j]  + bo[j]);
    float cn = f * c_prev[idx] + ii * cd;
    c_out[idx] = cn;
    h_out[idx] = o * tanhf(cn);
}

// ---------------------------------------------------------------------------
// Kernel 4: output projection  all_y = all_h @ Wout + b
// M=16384, N=10000, K=1024.  BM=BN=128, BK=16, 256 threads, 8x8 microtile.
// ---------------------------------------------------------------------------
__global__ void __launch_bounds__(256)
ygemm_kernel(const float* __restrict__ A,       // all_h [16384][1024]
             const float* __restrict__ Wout,    // [1024][10000]
             const float* __restrict__ bout,    // [10000]
             float* __restrict__ Y) {           // all_y [16384][10000]
    __shared__ float As[16][128];   // [k][m]
    __shared__ float Bs[16][128];   // [k][n]

    const int n0 = blockIdx.x * 128;
    const int m0 = blockIdx.y * 128;
    const int tid = threadIdx.x;
    const int tm = tid >> 4;        // 0..15
    const int tn = tid & 15;        // 0..15

    float acc[8][8];
#pragma unroll
    for (int a = 0; a < 8; ++a)
#pragma unroll
        for (int b = 0; b < 8; ++b) acc[a][b] = 0.0f;

    for (int k0 = 0; k0 < HH; k0 += 16) {
        // A tile: 128 rows x 16 k = 512 float4, 2 per thread
#pragma unroll
        for (int j = 0; j < 2; ++j) {
            int i = tid * 2 + j;              // 0..511
            int row = i >> 2;                 // 0..127
            int kq  = (i & 3) * 4;
            float4 v = *(const float4*)(A + (size_t)(m0 + row) * HH + k0 + kq);
            As[kq + 0][row] = v.x;
            As[kq + 1][row] = v.y;
            As[kq + 2][row] = v.z;
            As[kq + 3][row] = v.w;
        }
        // B tile: 16 k x 128 n = 512 float4, 2 per thread (n-guarded)
#pragma unroll
        for (int j = 0; j < 2; ++j) {
            int i = tid * 2 + j;              // 0..511
            int kk = i >> 5;                  // 0..15
            int nq = (i & 31) * 4;            // 0..124
            int n = n0 + nq;
            float4 v = make_float4(0.f, 0.f, 0.f, 0.f);
            if (n < VV)
                v = *(const float4*)(Wout + (size_t)(k0 + kk) * VV + n);
            *(float4*)&Bs[kk][nq] = v;
        }
        __syncthreads();

#pragma unroll
        for (int kk = 0; kk < 16; ++kk) {
            float av[8], bv[8];
            *(float4*)(av)     = *(const float4*)&As[kk][tm * 8];
            *(float4*)(av + 4) = *(const float4*)&As[kk][tm * 8 + 4];
            *(float4*)(bv)     = *(const float4*)&Bs[kk][tn * 8];
            *(float4*)(bv + 4) = *(const float4*)&Bs[kk][tn * 8 + 4];
#pragma unroll
            for (int mi = 0; mi < 8; ++mi)
#pragma unroll
                for (int ni = 0; ni < 8; ++ni)
                    acc[mi][ni] += av[mi] * bv[ni];
        }
        __syncthreads();
    }

#pragma unroll
    for (int mi = 0; mi < 8; ++mi) {
        int m = m0 + tm * 8 + mi;
        float* yp = Y + (size_t)m * VV;
#pragma unroll
        for (int ni = 0; ni < 8; ++ni) {
            int n = n0 + tn * 8 + ni;
            if (n < VV) yp[n] = acc[mi][ni] + bout[n];
        }
    }
}

// ---------------------------------------------------------------------------
// Launch
// Inputs (metadata order): x, h, c, emb, Wf_w, Wf_b, Wi_w, Wi_b, Wc_w, Wc_b,
//                          Wo_w, Wo_b, Wout_w, Wout_b
// Output: concat(all_h [T,B,H], all_c [T,B,H], all_y [T,B,V]) as float32
// ---------------------------------------------------------------------------
extern "C" void kernel_launch(void* const* d_in, const int* in_sizes, int n_in,
                              void* d_out, int out_size) {
    const int*   x     = (const int*)d_in[0];
    const float* h0    = (const float*)d_in[1];
    const float* c0    = (const float*)d_in[2];
    const float* emb   = (const float*)d_in[3];
    const float* Wf_w  = (const float*)d_in[4];
    const float* Wf_b  = (const float*)d_in[5];
    const float* Wi_w  = (const float*)d_in[6];
    const float* Wi_b  = (const float*)d_in[7];
    const float* Wc_w  = (const float*)d_in[8];
    const float* Wc_b  = (const float*)d_in[9];
    const float* Wo_w  = (const float*)d_in[10];
    const float* Wo_b  = (const float*)d_in[11];
    const float* Woutw = (const float*)d_in[12];
    const float* Woutb = (const float*)d_in[13];

    float* out   = (float*)d_out;
    float* all_h = out;
    float* all_c = out + (size_t)TT * BB * HH;
    float* all_y = out + (size_t)2 * TT * BB * HH;

    // 1) gather embeddings
    embed_kernel<<<TT * BB, 128>>>(x, emb);

    // 2) sequential recurrence
    for (int t = 0; t < TT; ++t) {
        const float* h_prev = (t == 0) ? h0 : all_h + (size_t)(t - 1) * BB * HH;
        const float* c_prev = (t == 0) ? c0 : all_c + (size_t)(t - 1) * BB * HH;
        gate_gemm_kernel<<<128, 128>>>(h_prev, t, Wf_w, Wi_w, Wc_w, Wo_w);
        cell_kernel<<<(BB * HH) / 256, 256>>>(c_prev, Wf_b, Wi_b, Wc_b, Wo_b,
                                              all_h + (size_t)t * BB * HH,
                                              all_c + (size_t)t * BB * HH);
    }

    // 3) one big output-projection GEMM over all timesteps
    dim3 yg((VV + 127) / 128, (TT * BB) / 128);   // 79 x 128
    ygemm_kernel<<<yg, 256>>>(all_h, Woutw, Woutb, all_y);
}

// round 5
// speedup vs baseline: 1.6778x; 1.6778x over previous
#include <cuda_runtime.h>
#include <cuda_bf16.h>
#include <cstdint>

// Problem constants
#define TT 256
#define BB 64
#define EE 512
#define HH 1024
#define VV 10000
#define G4 4096      // 4*H
#define KS 8         // split-K factor for recurrent GEMM
#define KC 128       // K chunk per split (8*128 = 1024 = H)

// Scratch (no cudaMalloc allowed): device globals
__device__ float g_xemb[(size_t)TT * BB * EE];    // [T*B][E]      33.5 MB
__device__ float g_gx  [(size_t)TT * BB * G4];    // [T*B][4H]     256  MB  (x@W_x + bias)
__device__ float g_part[(size_t)KS * BB * G4];    // [ks][B][4H]   8    MB  (h@W_h partials)

// ---------------------------------------------------------------------------
// Kernel 1: embedding gather  x_emb[t*B+b][:] = emb[x[t][b]][:]
// ---------------------------------------------------------------------------
__global__ void embed_kernel(const int* __restrict__ x, const float* __restrict__ emb) {
    int row = blockIdx.x;                 // t*B + b
    int idx = x[row];
    const float4* src = (const float4*)(emb + (size_t)idx * EE);
    float4* dst = (float4*)(g_xemb + (size_t)row * EE);
    dst[threadIdx.x] = src[threadIdx.x];
}

// ---------------------------------------------------------------------------
// Kernel 2: gx = x_emb @ W_x + b_g   (hoisted, no sequential dependency)
// M=16384, N=4096 (gate-major), K=512. BM=BN=128, BK=16, 256 thr, 8x8 micro.
// W_x = rows [H .. H+E) of each gate's [E+H, H] weight.
// ---------------------------------------------------------------------------
__global__ void __launch_bounds__(256)
gx_gemm_kernel(const float* __restrict__ Wf, const float* __restrict__ Wi,
               const float* __restrict__ Wc, const float* __restrict__ Wo,
               const float* __restrict__ bf, const float* __restrict__ bi,
               const float* __restrict__ bc, const float* __restrict__ bo) {
    __shared__ float As[16][128];
    __shared__ float Bs[16][128];

    const int gate = blockIdx.x >> 3;           // 0..3
    const int col0 = (blockIdx.x & 7) * 128;    // within gate's H
    const int m0 = blockIdx.y * 128;
    const float* W = (gate == 0) ? Wf : (gate == 1) ? Wi : (gate == 2) ? Wc : Wo;
    const float* bias = (gate == 0) ? bf : (gate == 1) ? bi : (gate == 2) ? bc : bo;

    const int tid = threadIdx.x;
    const int tm = tid >> 4;        // 0..15
    const int tn = tid & 15;        // 0..15

    float acc[8][8];
#pragma unroll
    for (int a = 0; a < 8; ++a)
#pragma unroll
        for (int b = 0; b < 8; ++b) acc[a][b] = 0.0f;

    for (int k0 = 0; k0 < EE; k0 += 16) {
        // A tile: 128 rows x 16 k, from g_xemb (row stride 512)
#pragma unroll
        for (int j = 0; j < 2; ++j) {
            int i = tid * 2 + j;              // 0..511
            int row = i >> 2;                 // 0..127
            int kq  = (i & 3) * 4;
            float4 v = *(const float4*)(g_xemb + (size_t)(m0 + row) * EE + k0 + kq);
            As[kq + 0][row] = v.x;
            As[kq + 1][row] = v.y;
            As[kq + 2][row] = v.z;
            As[kq + 3][row] = v.w;
        }
        // B tile: 16 k x 128 n from W rows (H + k)
#pragma unroll
        for (int j = 0; j < 2; ++j) {
            int i = tid + j * 256;            // 0..511
            int kk = i >> 5;                  // 0..15
            int nq = (i & 31) * 4;            // 0..124
            float4 v = *(const float4*)(W + (size_t)(HH + k0 + kk) * HH + col0 + nq);
            *(float4*)&Bs[kk][nq] = v;
        }
        __syncthreads();

#pragma unroll
        for (int kk = 0; kk < 16; ++kk) {
            float av[8], bv[8];
            *(float4*)(av)     = *(const float4*)&As[kk][tm * 8];
            *(float4*)(av + 4) = *(const float4*)&As[kk][tm * 8 + 4];
            *(float4*)(bv)     = *(const float4*)&Bs[kk][tn * 8];
            *(float4*)(bv + 4) = *(const float4*)&Bs[kk][tn * 8 + 4];
#pragma unroll
            for (int mi = 0; mi < 8; ++mi)
#pragma unroll
                for (int ni = 0; ni < 8; ++ni)
                    acc[mi][ni] += av[mi] * bv[ni];
        }
        __syncthreads();
    }

#pragma unroll
    for (int mi = 0; mi < 8; ++mi) {
        int m = m0 + tm * 8 + mi;
        float* gp = g_gx + (size_t)m * G4 + gate * HH + col0;
#pragma unroll
        for (int ni = 0; ni < 8; ++ni) {
            int n = tn * 8 + ni;
            gp[n] = acc[mi][ni] + bias[col0 + n];
        }
    }
}

// ---------------------------------------------------------------------------
// Kernel 3: per-step recurrent GEMM  g_part[ks] = h_prev @ W_h[kchunk]
// M=64, N=4096, K=1024. Tile 64x128, split-K=8 -> 256 CTAs, 128 thr, 8x8 micro.
// Double-buffered smem, 1 sync/iter, register-prefetched global loads.
// ---------------------------------------------------------------------------
__global__ void __launch_bounds__(128)
gate_hgemm_kernel(const float* __restrict__ h_prev,
                  const float* __restrict__ Wf, const float* __restrict__ Wi,
                  const float* __restrict__ Wc, const float* __restrict__ Wo) {
    __shared__ float As[2][16][64];    // [buf][k][m]   2x4KB
    __shared__ float Bs[2][16][128];   // [buf][k][n]   2x8KB

    const int bx = blockIdx.x;            // 0..255
    const int nt = bx & 31;               // n-tile
    const int ks = bx >> 5;               // k-split 0..7
    const int gate = nt >> 3;
    const int col0 = (nt & 7) * 128;
    const float* W = (gate == 0) ? Wf : (gate == 1) ? Wi : (gate == 2) ? Wc : Wo;

    const int tid = threadIdx.x;
    const int tm = tid >> 4;              // 0..7
    const int tn = tid & 15;              // 0..15
    const int kbase = ks * KC;

    // load-index precompute
    const int a_row = tid >> 1;                 // 0..63  (2 float4 per thread)
    const int a_kq  = (tid & 1) * 8;            // 0 or 8
    const float* a_src = h_prev + (size_t)a_row * HH + kbase + a_kq;

    float acc[8][8];
#pragma unroll
    for (int a = 0; a < 8; ++a)
#pragma unroll
        for (int b = 0; b < 8; ++b) acc[a][b] = 0.0f;

    float4 ra0, ra1, rb0, rb1, rb2, rb3;

    // prologue: tile 0 -> regs -> buf 0
    {
        ra0 = *(const float4*)(a_src);
        ra1 = *(const float4*)(a_src + 4);
#pragma unroll
        for (int j = 0; j < 4; ++j) {
            int i = tid + j * 128;
            int kk = i >> 5;
            int nq = (i & 31) * 4;
            float4 v = *(const float4*)(W + (size_t)(kbase + kk) * HH + col0 + nq);
            if (j == 0) rb0 = v; else if (j == 1) rb1 = v; else if (j == 2) rb2 = v; else rb3 = v;
        }
        As[0][a_kq + 0][a_row] = ra0.x;  As[0][a_kq + 1][a_row] = ra0.y;
        As[0][a_kq + 2][a_row] = ra0.z;  As[0][a_kq + 3][a_row] = ra0.w;
        As[0][a_kq + 4][a_row] = ra1.x;  As[0][a_kq + 5][a_row] = ra1.y;
        As[0][a_kq + 6][a_row] = ra1.z;  As[0][a_kq + 7][a_row] = ra1.w;
#pragma unroll
        for (int j = 0; j < 4; ++j) {
            int i = tid + j * 128;
            int kk = i >> 5;
            int nq = (i & 31) * 4;
            float4 v = (j == 0) ? rb0 : (j == 1) ? rb1 : (j == 2) ? rb2 : rb3;
            *(float4*)&Bs[0][kk][nq] = v;
        }
    }

#pragma unroll 1
    for (int it = 0; it < KC / 16; ++it) {       // 8 iterations
        __syncthreads();
        const int cur = it & 1;

        if (it < KC / 16 - 1) {                  // prefetch next tile -> regs
            int k0 = kbase + (it + 1) * 16;
            ra0 = *(const float4*)(h_prev + (size_t)a_row * HH + k0 + a_kq);
            ra1 = *(const float4*)(h_prev + (size_t)a_row * HH + k0 + a_kq + 4);
#pragma unroll
            for (int j = 0; j < 4; ++j) {
                int i = tid + j * 128;
                int kk = i >> 5;
                int nq = (i & 31) * 4;
                float4 v = *(const float4*)(W + (size_t)(k0 + kk) * HH + col0 + nq);
                if (j == 0) rb0 = v; else if (j == 1) rb1 = v; else if (j == 2) rb2 = v; else rb3 = v;
            }
        }

        // compute from buf[cur]
#pragma unroll
        for (int kk = 0; kk < 16; ++kk) {
            float4 a0 = *(const float4*)&As[cur][kk][tm * 4];
            float4 a1 = *(const float4*)&As[cur][kk][tm * 4 + 32];
            float4 b0 = *(const float4*)&Bs[cur][kk][tn * 4];
            float4 b1 = *(const float4*)&Bs[cur][kk][tn * 4 + 64];
            float av[8] = {a0.x, a0.y, a0.z, a0.w, a1.x, a1.y, a1.z, a1.w};
            float bv[8] = {b0.x, b0.y, b0.z, b0.w, b1.x, b1.y, b1.z, b1.w};
#pragma unroll
            for (int mi = 0; mi < 8; ++mi)
#pragma unroll
                for (int ni = 0; ni < 8; ++ni)
                    acc[mi][ni] += av[mi] * bv[ni];
        }

        if (it < KC / 16 - 1) {                  // regs -> buf[1-cur]
            int nxt = 1 - cur;
            As[nxt][a_kq + 0][a_row] = ra0.x;  As[nxt][a_kq + 1][a_row] = ra0.y;
            As[nxt][a_kq + 2][a_row] = ra0.z;  As[nxt][a_kq + 3][a_row] = ra0.w;
            As[nxt][a_kq + 4][a_row] = ra1.x;  As[nxt][a_kq + 5][a_row] = ra1.y;
            As[nxt][a_kq + 6][a_row] = ra1.z;  As[nxt][a_kq + 7][a_row] = ra1.w;
#pragma unroll
            for (int j = 0; j < 4; ++j) {
                int i = tid + j * 128;
                int kk = i >> 5;
                int nq = (i & 31) * 4;
                float4 v = (j == 0) ? rb0 : (j == 1) ? rb1 : (j == 2) ? rb2 : rb3;
                *(float4*)&Bs[nxt][kk][nq] = v;
            }
        }
    }

    // epilogue: write split-K partial
    float* base = g_part + (size_t)ks * BB * G4 + (size_t)(gate * HH + col0);
#pragma unroll
    for (int mi = 0; mi < 8; ++mi) {
        int m = tm * 4 + (mi & 3) + ((mi >> 2) * 32);
        float* r = base + (size_t)m * G4;
        *(float4*)(r + tn * 4)      = make_float4(acc[mi][0], acc[mi][1], acc[mi][2], acc[mi][3]);
        *(float4*)(r + tn * 4 + 64) = make_float4(acc[mi][4], acc[mi][5], acc[mi][6], acc[mi][7]);
    }
}

// ---------------------------------------------------------------------------
// Kernel 4: LSTM cell: sum split-K partials + gx, activations, state update
// ---------------------------------------------------------------------------
__device__ __forceinline__ float sigmoidf_(float x) {
    return 1.0f / (1.0f + __expf(-x));
}

__global__ void __launch_bounds__(256)
cell_kernel(const float* __restrict__ c_prev, int t,
            float* __restrict__ h_out, float* __restrict__ c_out) {
    int idx = blockIdx.x * blockDim.x + threadIdx.x;  // 0..B*H-1
    int b = idx >> 10;
    int j = idx & (HH - 1);
    const float* gx = g_gx + (size_t)(t * BB + b) * G4;
    const float* pb = g_part + (size_t)b * G4;

    float g[4];
#pragma unroll
    for (int gi = 0; gi < 4; ++gi) {
        int off = gi * HH + j;
        float s = gx[off];
#pragma unroll
        for (int sp = 0; sp < KS; ++sp)
            s += pb[(size_t)sp * BB * G4 + off];
        g[gi] = s;
    }
    float f  = sigmoidf_(g[0]);
    float ii = sigmoidf_(g[1]);
    float cd = tanhf(g[2]);
    float o  = sigmoidf_(g[3]);
    float cn = f * c_prev[idx] + ii * cd;
    c_out[idx] = cn;
    h_out[idx] = o * tanhf(cn);
}

// ---------------------------------------------------------------------------
// Kernel 5: output projection  all_y = all_h @ Wout + b   (unchanged, ~74 TF/s)
// ---------------------------------------------------------------------------
__global__ void __launch_bounds__(256)
ygemm_kernel(const float* __restrict__ A,
             const float* __restrict__ Wout,
             const float* __restrict__ bout,
             float* __restrict__ Y) {
    __shared__ float As[16][128];
    __shared__ float Bs[16][128];

    const int n0 = blockIdx.x * 128;
    const int m0 = blockIdx.y * 128;
    const int tid = threadIdx.x;
    const int tm = tid >> 4;
    const int tn = tid & 15;

    float acc[8][8];
#pragma unroll
    for (int a = 0; a < 8; ++a)
#pragma unroll
        for (int b = 0; b < 8; ++b) acc[a][b] = 0.0f;

    for (int k0 = 0; k0 < HH; k0 += 16) {
#pragma unroll
        for (int j = 0; j < 2; ++j) {
            int i = tid * 2 + j;
            int row = i >> 2;
            int kq  = (i & 3) * 4;
            float4 v = *(const float4*)(A + (size_t)(m0 + row) * HH + k0 + kq);
            As[kq + 0][row] = v.x;
            As[kq + 1][row] = v.y;
            As[kq + 2][row] = v.z;
            As[kq + 3][row] = v.w;
        }
#pragma unroll
        for (int j = 0; j < 2; ++j) {
            int i = tid * 2 + j;
            int kk = i >> 5;
            int nq = (i & 31) * 4;
            int n = n0 + nq;
            float4 v = make_float4(0.f, 0.f, 0.f, 0.f);
            if (n < VV)
                v = *(const float4*)(Wout + (size_t)(k0 + kk) * VV + n);
            *(float4*)&Bs[kk][nq] = v;
        }
        __syncthreads();

#pragma unroll
        for (int kk = 0; kk < 16; ++kk) {
            float av[8], bv[8];
            *(float4*)(av)     = *(const float4*)&As[kk][tm * 8];
            *(float4*)(av + 4) = *(const float4*)&As[kk][tm * 8 + 4];
            *(float4*)(bv)     = *(const float4*)&Bs[kk][tn * 8];
            *(float4*)(bv + 4) = *(const float4*)&Bs[kk][tn * 8 + 4];
#pragma unroll
            for (int mi = 0; mi < 8; ++mi)
#pragma unroll
                for (int ni = 0; ni < 8; ++ni)
                    acc[mi][ni] += av[mi] * bv[ni];
        }
        __syncthreads();
    }

#pragma unroll
    for (int mi = 0; mi < 8; ++mi) {
        int m = m0 + tm * 8 + mi;
        float* yp = Y + (size_t)m * VV;
#pragma unroll
        for (int ni = 0; ni < 8; ++ni) {
            int n = n0 + tn * 8 + ni;
            if (n < VV) yp[n] = acc[mi][ni] + bout[n];
        }
    }
}

// ---------------------------------------------------------------------------
// Launch
// ---------------------------------------------------------------------------
extern "C" void kernel_launch(void* const* d_in, const int* in_sizes, int n_in,
                              void* d_out, int out_size) {
    const int*   x     = (const int*)d_in[0];
    const float* h0    = (const float*)d_in[1];
    const float* c0    = (const float*)d_in[2];
    const float* emb   = (const float*)d_in[3];
    const float* Wf_w  = (const float*)d_in[4];
    const float* Wf_b  = (const float*)d_in[5];
    const float* Wi_w  = (const float*)d_in[6];
    const float* Wi_b  = (const float*)d_in[7];
    const float* Wc_w  = (const float*)d_in[8];
    const float* Wc_b  = (const float*)d_in[9];
    const float* Wo_w  = (const float*)d_in[10];
    const float* Wo_b  = (const float*)d_in[11];
    const float* Woutw = (const float*)d_in[12];
    const float* Woutb = (const float*)d_in[13];

    float* out   = (float*)d_out;
    float* all_h = out;
    float* all_c = out + (size_t)TT * BB * HH;
    float* all_y = out + (size_t)2 * TT * BB * HH;

    // 1) gather embeddings
    embed_kernel<<<TT * BB, 128>>>(x, emb);

    // 2) hoisted x-projection + bias: gx[T*B][4H]
    dim3 gxg(32, (TT * BB) / 128);   // 32 x 128
    gx_gemm_kernel<<<gxg, 256>>>(Wf_w, Wi_w, Wc_w, Wo_w, Wf_b, Wi_b, Wc_b, Wo_b);

    // 3) sequential recurrence (h-projection only, split-K=8)
    for (int t = 0; t < TT; ++t) {
        const float* h_prev = (t == 0) ? h0 : all_h + (size_t)(t - 1) * BB * HH;
        const float* c_prev = (t == 0) ? c0 : all_c + (size_t)(t - 1) * BB * HH;
        gate_hgemm_kernel<<<256, 128>>>(h_prev, Wf_w, Wi_w, Wc_w, Wo_w);
        cell_kernel<<<(BB * HH) / 256, 256>>>(c_prev, t,
                                              all_h + (size_t)t * BB * HH,
                                              all_c + (size_t)t * BB * HH);
    }

    // 4) one big output-projection GEMM over all timesteps
    dim3 yg((VV + 127) / 128, (TT * BB) / 128);   // 79 x 128
    ygemm_kernel<<<yg, 256>>>(all_h, Woutw, Woutb, all_y);
}

// round 6
// speedup vs baseline: 2.3762x; 1.4163x over previous
#include <cuda_runtime.h>
#include <cuda_bf16.h>
#include <cstdint>

// Problem constants
#define TT 256
#define BB 64
#define EE 512
#define HH 1024
#define VV 10000
#define G4 4096      // 4*H
#define NCTA 128
#define NTHR 512

// Scratch (no cudaMalloc allowed): device globals
__device__ float g_xemb[(size_t)TT * BB * EE];    // [T*B][E]   33.5 MB
__device__ float g_gx  [(size_t)TT * BB * G4];    // [T*B][4H]  256  MB  (x@W_x + bias)
__device__ unsigned g_bar_count;                  // zero-init
__device__ unsigned g_bar_phase;                  // monotonically grows across replays

// Dynamic smem layout (floats):
//   hs[2][16*1024]   : 0      .. 32767   (two h slabs, 64KB each... 2*16K floats)
//   sc[16][32][20]   : 32768  .. 43007   (split-K scratch, padded)
//   gsm[16][32]      : 43008  .. 43519
//   shp (unsigned)   : 43520
#define SMEM_FLOATS (43524)
#define SMEM_BYTES  (SMEM_FLOATS * 4)

// ---------------------------------------------------------------------------
// Kernel 1: embedding gather
// ---------------------------------------------------------------------------
__global__ void embed_kernel(const int* __restrict__ x, const float* __restrict__ emb) {
    int row = blockIdx.x;                 // t*B + b
    int idx = x[row];
    const float4* src = (const float4*)(emb + (size_t)idx * EE);
    float4* dst = (float4*)(g_xemb + (size_t)row * EE);
    dst[threadIdx.x] = src[threadIdx.x];
}

// ---------------------------------------------------------------------------
// Kernel 2: gx = x_emb @ W_x + b_g   (hoisted; W_x = rows [H, H+E) of gate W)
// M=16384, N=4096 gate-major, K=512. BM=BN=128, BK=16, 256 thr, 8x8 micro.
// ---------------------------------------------------------------------------
__global__ void __launch_bounds__(256)
gx_gemm_kernel(const float* __restrict__ Wf, const float* __restrict__ Wi,
               const float* __restrict__ Wc, const float* __restrict__ Wo,
               const float* __restrict__ bf, const float* __restrict__ bi,
               const float* __restrict__ bc, const float* __restrict__ bo) {
    __shared__ float As[16][128];
    __shared__ float Bs[16][128];

    const int gate = blockIdx.x >> 3;
    const int col0 = (blockIdx.x & 7) * 128;
    const int m0 = blockIdx.y * 128;
    const float* W = (gate == 0) ? Wf : (gate == 1) ? Wi : (gate == 2) ? Wc : Wo;
    const float* bias = (gate == 0) ? bf : (gate == 1) ? bi : (gate == 2) ? bc : bo;

    const int tid = threadIdx.x;
    const int tm = tid >> 4;
    const int tn = tid & 15;

    float acc[8][8];
#pragma unroll
    for (int a = 0; a < 8; ++a)
#pragma unroll
        for (int b = 0; b < 8; ++b) acc[a][b] = 0.0f;

    for (int k0 = 0; k0 < EE; k0 += 16) {
#pragma unroll
        for (int j = 0; j < 2; ++j) {
            int i = tid * 2 + j;
            int row = i >> 2;
            int kq  = (i & 3) * 4;
            float4 v = *(const float4*)(g_xemb + (size_t)(m0 + row) * EE + k0 + kq);
            As[kq + 0][row] = v.x;
            As[kq + 1][row] = v.y;
            As[kq + 2][row] = v.z;
            As[kq + 3][row] = v.w;
        }
#pragma unroll
        for (int j = 0; j < 2; ++j) {
            int i = tid + j * 256;
            int kk = i >> 5;
            int nq = (i & 31) * 4;
            float4 v = *(const float4*)(W + (size_t)(HH + k0 + kk) * HH + col0 + nq);
            *(float4*)&Bs[kk][nq] = v;
        }
        __syncthreads();

#pragma unroll
        for (int kk = 0; kk < 16; ++kk) {
            float av[8], bv[8];
            *(float4*)(av)     = *(const float4*)&As[kk][tm * 8];
            *(float4*)(av + 4) = *(const float4*)&As[kk][tm * 8 + 4];
            *(float4*)(bv)     = *(const float4*)&Bs[kk][tn * 8];
            *(float4*)(bv + 4) = *(const float4*)&Bs[kk][tn * 8 + 4];
#pragma unroll
            for (int mi = 0; mi < 8; ++mi)
#pragma unroll
                for (int ni = 0; ni < 8; ++ni)
                    acc[mi][ni] += av[mi] * bv[ni];
        }
        __syncthreads();
    }

#pragma unroll
    for (int mi = 0; mi < 8; ++mi) {
        int m = m0 + tm * 8 + mi;
        float* gp = g_gx + (size_t)m * G4 + gate * HH + col0;
#pragma unroll
        for (int ni = 0; ni < 8; ++ni) {
            int n = tn * 8 + ni;
            gp[n] = acc[mi][ni] + bias[col0 + n];
        }
    }
}

// ---------------------------------------------------------------------------
// Kernel 3: persistent LSTM recurrence, 128 CTAs x 512 threads.
// CTA n owns H-columns [n*8, n*8+8) for ALL 4 gates (cell is CTA-local).
// Thread (kg = tid>>5, c = tid&31): gate = c>>3, jo = c&7.
// W_h slice (64 k-values x 1 column) lives in registers for all 256 steps.
// One grid barrier per timestep.
// ---------------------------------------------------------------------------
__device__ __forceinline__ float sigmoidf_(float x) {
    return 1.0f / (1.0f + __expf(-x));
}

__device__ __forceinline__ void slab_load_async(float* dst, const float* hsrc,
                                                int rb, int tid) {
#pragma unroll
    for (int q = 0; q < 8; ++q) {
        int idx = tid + q * NTHR;        // 0..4095
        int row = idx >> 8;              // 0..15
        int c4  = idx & 255;             // float4 index in row
        const float* src = hsrc + (size_t)(rb * 16 + row) * HH + c4 * 4;
        unsigned dsta = (unsigned)__cvta_generic_to_shared(dst + row * HH + c4 * 4);
        asm volatile("cp.async.cg.shared.global [%0], [%1], 16;\n"
                     :: "r"(dsta), "l"(src) : "memory");
    }
}

__device__ __forceinline__ void grid_bar(unsigned target) {
    __syncthreads();
    if (threadIdx.x == 0) {
        __threadfence();
        unsigned old = atomicAdd(&g_bar_count, 1u);
        if (old == NCTA - 1) {
            atomicExch(&g_bar_count, 0u);
            __threadfence();
            atomicAdd(&g_bar_phase, 1u);
        } else {
            while ((int)(*((volatile unsigned*)&g_bar_phase) - target) < 0) {}
            __threadfence();
        }
    }
    __syncthreads();
}

__global__ void __launch_bounds__(NTHR, 1)
lstm_persistent_kernel(const float* __restrict__ h0, const float* __restrict__ c0,
                       const float* __restrict__ Wf, const float* __restrict__ Wi,
                       const float* __restrict__ Wc, const float* __restrict__ Wo,
                       float* __restrict__ all_h, float* __restrict__ all_c) {
    extern __shared__ float smem[];
    float* hs0 = smem;
    float* hs1 = smem + 16384;
    float* sc  = smem + 32768;          // [16][32][20] padded
    float* gsm = smem + 43008;          // [16][32]
    unsigned* shp = (unsigned*)(smem + 43520);

    const int tid = threadIdx.x;
    const int kg  = tid >> 5;           // 0..15 (warp id = K group)
    const int c   = tid & 31;           // gate*8 + jo
    const int gate = c >> 3;
    const int jo   = c & 7;
    const int n    = blockIdx.x;        // 0..127
    const int j    = n * 8 + jo;        // H column

    const float* Wg = (gate == 0) ? Wf : (gate == 1) ? Wi : (gate == 2) ? Wc : Wo;

    // One-time: W_h slice into registers (rows 0..H-1 of W are the h-part)
    float w[64];
#pragma unroll
    for (int kk = 0; kk < 64; ++kk)
        w[kk] = Wg[(size_t)(kg * 64 + kk) * HH + j];

    if (tid == 0) shp[0] = *((volatile unsigned*)&g_bar_phase);
    __syncthreads();
    const unsigned phase_base = shp[0];

    // reduce-phase indices
    const int r_ml = tid >> 5;          // 0..15 (row within block)
    const int r_c  = tid & 31;
    const int r_cgl = (r_c >> 3) * HH + n * 8 + (r_c & 7);   // column in [0,4H)

    for (int t = 0; t < TT; ++t) {
        const float* hsrc = (t == 0) ? h0 : all_h + (size_t)(t - 1) * BB * HH;
        const float* csrc = (t == 0) ? c0 : all_c + (size_t)(t - 1) * BB * HH;
        float* hdst = all_h + (size_t)t * BB * HH;
        float* cdst = all_c + (size_t)t * BB * HH;

        // preload slab 0
        slab_load_async(hs0, hsrc, 0, tid);
        asm volatile("cp.async.commit_group;\n" ::: "memory");
        asm volatile("cp.async.wait_group 0;\n" ::: "memory");
        __syncthreads();

#pragma unroll 1
        for (int rb = 0; rb < 4; ++rb) {
            float* cur = (rb & 1) ? hs1 : hs0;
            float* nxt = (rb & 1) ? hs0 : hs1;
            if (rb < 3) {
                slab_load_async(nxt, hsrc, rb + 1, tid);
                asm volatile("cp.async.commit_group;\n" ::: "memory");
            }

            // ---- compute: 16 rows, 64-k partial dot with register W
            const float* hbase = cur + kg * 64;
#pragma unroll 1
            for (int mi = 0; mi < 16; ++mi) {
                const float4* h4 = (const float4*)(hbase + mi * HH);
                float a0 = 0.f, a1 = 0.f, a2 = 0.f, a3 = 0.f;
#pragma unroll
                for (int q = 0; q < 16; ++q) {
                    float4 v = h4[q];
                    a0 = fmaf(v.x, w[4 * q + 0], a0);
                    a1 = fmaf(v.y, w[4 * q + 1], a1);
                    a2 = fmaf(v.z, w[4 * q + 2], a2);
                    a3 = fmaf(v.w, w[4 * q + 3], a3);
                }
                sc[(mi * 32 + c) * 20 + kg] = (a0 + a1) + (a2 + a3);
            }
            __syncthreads();

            // ---- reduce 16 K-groups + add gx (bias folded in)
            {
                const float* p = sc + (r_ml * 32 + r_c) * 20;
                float4 s0 = *(const float4*)(p);
                float4 s1 = *(const float4*)(p + 4);
                float4 s2 = *(const float4*)(p + 8);
                float4 s3 = *(const float4*)(p + 12);
                float s = ((s0.x + s0.y) + (s0.z + s0.w))
                        + ((s1.x + s1.y) + (s1.z + s1.w))
                        + ((s2.x + s2.y) + (s2.z + s2.w))
                        + ((s3.x + s3.y) + (s3.z + s3.w));
                int mrow = rb * 16 + r_ml;
                s += g_gx[((size_t)t * BB + mrow) * G4 + r_cgl];
                gsm[r_ml * 32 + r_c] = s;
            }
            __syncthreads();

            // ---- fused cell for these 16 rows (128 threads active)
            if (tid < 128) {
                int ml = tid >> 3;
                int jj = tid & 7;
                int mrow = rb * 16 + ml;
                const float* g = gsm + ml * 32;
                float f  = sigmoidf_(g[jj]);
                float ii = sigmoidf_(g[8 + jj]);
                float cd = tanhf(g[16 + jj]);
                float o  = sigmoidf_(g[24 + jj]);
                size_t off = (size_t)mrow * HH + n * 8 + jj;
                float cn = f * csrc[off] + ii * cd;
                cdst[off] = cn;
                hdst[off] = o * tanhf(cn);
            }
            if (rb < 3) asm volatile("cp.async.wait_group 0;\n" ::: "memory");
            __syncthreads();
        }

        grid_bar(phase_base + (unsigned)t + 1u);
    }
}

// ---------------------------------------------------------------------------
// Kernel 4: output projection  all_y = all_h @ Wout + b  (~74 TF/s fp32)
// ---------------------------------------------------------------------------
__global__ void __launch_bounds__(256)
ygemm_kernel(const float* __restrict__ A,
             const float* __restrict__ Wout,
             const float* __restrict__ bout,
             float* __restrict__ Y) {
    __shared__ float As[16][128];
    __shared__ float Bs[16][128];

    const int n0 = blockIdx.x * 128;
    const int m0 = blockIdx.y * 128;
    const int tid = threadIdx.x;
    const int tm = tid >> 4;
    const int tn = tid & 15;

    float acc[8][8];
#pragma unroll
    for (int a = 0; a < 8; ++a)
#pragma unroll
        for (int b = 0; b < 8; ++b) acc[a][b] = 0.0f;

    for (int k0 = 0; k0 < HH; k0 += 16) {
#pragma unroll
        for (int j = 0; j < 2; ++j) {
            int i = tid * 2 + j;
            int row = i >> 2;
            int kq  = (i & 3) * 4;
            float4 v = *(const float4*)(A + (size_t)(m0 + row) * HH + k0 + kq);
            As[kq + 0][row] = v.x;
            As[kq + 1][row] = v.y;
            As[kq + 2][row] = v.z;
            As[kq + 3][row] = v.w;
        }
#pragma unroll
        for (int j = 0; j < 2; ++j) {
            int i = tid * 2 + j;
            int kk = i >> 5;
            int nq = (i & 31) * 4;
            int nn = n0 + nq;
            float4 v = make_float4(0.f, 0.f, 0.f, 0.f);
            if (nn < VV)
                v = *(const float4*)(Wout + (size_t)(k0 + kk) * VV + nn);
            *(float4*)&Bs[kk][nq] = v;
        }
        __syncthreads();

#pragma unroll
        for (int kk = 0; kk < 16; ++kk) {
            float av[8], bv[8];
            *(float4*)(av)     = *(const float4*)&As[kk][tm * 8];
            *(float4*)(av + 4) = *(const float4*)&As[kk][tm * 8 + 4];
            *(float4*)(bv)     = *(const float4*)&Bs[kk][tn * 8];
            *(float4*)(bv + 4) = *(const float4*)&Bs[kk][tn * 8 + 4];
#pragma unroll
            for (int mi = 0; mi < 8; ++mi)
#pragma unroll
                for (int ni = 0; ni < 8; ++ni)
                    acc[mi][ni] += av[mi] * bv[ni];
        }
        __syncthreads();
    }

#pragma unroll
    for (int mi = 0; mi < 8; ++mi) {
        int m = m0 + tm * 8 + mi;
        float* yp = Y + (size_t)m * VV;
#pragma unroll
        for (int ni = 0; ni < 8; ++ni) {
            int nn = n0 + tn * 8 + ni;
            if (nn < VV) yp[nn] = acc[mi][ni] + bout[nn];
        }
    }
}

// ---------------------------------------------------------------------------
// Launch
// ---------------------------------------------------------------------------
extern "C" void kernel_launch(void* const* d_in, const int* in_sizes, int n_in,
                              void* d_out, int out_size) {
    const int*   x     = (const int*)d_in[0];
    const float* h0    = (const float*)d_in[1];
    const float* c0    = (const float*)d_in[2];
    const float* emb   = (const float*)d_in[3];
    const float* Wf_w  = (const float*)d_in[4];
    const float* Wf_b  = (const float*)d_in[5];
    const float* Wi_w  = (const float*)d_in[6];
    const float* Wi_b  = (const float*)d_in[7];
    const float* Wc_w  = (const float*)d_in[8];
    const float* Wc_b  = (const float*)d_in[9];
    const float* Wo_w  = (const float*)d_in[10];
    const float* Wo_b  = (const float*)d_in[11];
    const float* Woutw = (const float*)d_in[12];
    const float* Woutb = (const float*)d_in[13];

    float* out   = (float*)d_out;
    float* all_h = out;
    float* all_c = out + (size_t)TT * BB * HH;
    float* all_y = out + (size_t)2 * TT * BB * HH;

    cudaFuncSetAttribute(lstm_persistent_kernel,
                         cudaFuncAttributeMaxDynamicSharedMemorySize, SMEM_BYTES);

    // 1) gather embeddings
    embed_kernel<<<TT * BB, 128>>>(x, emb);

    // 2) hoisted x-projection + bias: gx[T*B][4H]
    dim3 gxg(32, (TT * BB) / 128);
    gx_gemm_kernel<<<gxg, 256>>>(Wf_w, Wi_w, Wc_w, Wo_w, Wf_b, Wi_b, Wc_b, Wo_b);

    // 3) entire recurrence in ONE persistent kernel (grid barrier per step)
    lstm_persistent_kernel<<<NCTA, NTHR, SMEM_BYTES>>>(h0, c0,
                                                       Wf_w, Wi_w, Wc_w, Wo_w,
                                                       all_h, all_c);

    // 4) one big output-projection GEMM over all timesteps
    dim3 yg((VV + 127) / 128, (TT * BB) / 128);
    ygemm_kernel<<<yg, 256>>>(all_h, Woutw, Woutb, all_y);
}